// round 15
// baseline (speedup 1.0000x reference)
#include <cuda_runtime.h>
#include <cuda_bf16.h>

#define NN 100000
#define EE 3200000
#define DD 16
#define EPSV 1e-5f
#define DEGB 256
#define MAXDEG 128           // Poisson(32): P(deg>=96) ~ 1e-19; 128 is safe
#define NCHUNK 1563          // ceil(NN/64) 64-node chunks
#define PBLOCKS 1184         // 8 blocks/SM * 148 SMs
#define SORTBLK 148          // 1 block/SM -> co-residency guaranteed

typedef unsigned long long ull;

// packed f32x2 helpers (PTX-only instructions; non-volatile so ptxas reorders)
__device__ __forceinline__ ull pk2(float lo, float hi) {
    ull r; asm("mov.b64 %0, {%1, %2};" : "=l"(r) : "f"(lo), "f"(hi)); return r;
}
__device__ __forceinline__ void upk2(ull v, float& lo, float& hi) {
    asm("mov.b64 {%0, %1}, %2;" : "=f"(lo), "=f"(hi) : "l"(v));
}
__device__ __forceinline__ ull add2(ull a, ull b) {
    ull r; asm("add.rn.f32x2 %0, %1, %2;" : "=l"(r) : "l"(a), "l"(b)); return r;
}
__device__ __forceinline__ ull fma2(ull a, ull b, ull c) {
    ull r; asm("fma.rn.f32x2 %0, %1, %2, %3;" : "=l"(r) : "l"(a), "l"(b), "l"(c)); return r;
}

// ---- static device scratch (allocation-free rule) ----
__device__ int      g_cursor[NN];          // per-node fill cursor == final degree
__device__ int      g_deghist[DEGB];
__device__ int      g_degcur[DEGB];        // claim counters (start at 0)
__device__ int      g_tickets[8];          // per-iteration ticket counters
__device__ int      g_bar;                 // software grid barrier arrive count
__device__ int4     g_nodeinfo[NN];        // {node, start, end, 0}, degree-sorted
__device__ int2     g_perm[NN * MAXDEG];   // fixed 128-record slot per node
__device__ float    g_bufA[NN * DD];
__device__ float    g_bufB[NN * DD];

// ---------------- build ----------------

__global__ void zero_kernel() {
    int i = blockIdx.x * blockDim.x + threadIdx.x;
    if (i < NN) g_cursor[i] = 0;
    if (i < DEGB) { g_deghist[i] = 0; g_degcur[i] = 0; }
    if (i < 8) g_tickets[i] = 0;
    if (i == 8) g_bar = 0;
}

// 4 edges per thread; slot-addressed scatter (no offsets needed)
__global__ void scatter_kernel(const int4* __restrict__ src4,
                               const int4* __restrict__ dst4,
                               const float4* __restrict__ attr4) {
    int i = blockIdx.x * blockDim.x + threadIdx.x;
    if (i < EE / 4) {
        int4   s = src4[i];
        int4   d = dst4[i];
        float4 a = attr4[i];
        int p0 = atomicAdd(&g_cursor[d.x], 1);
        int p1 = atomicAdd(&g_cursor[d.y], 1);
        int p2 = atomicAdd(&g_cursor[d.z], 1);
        int p3 = atomicAdd(&g_cursor[d.w], 1);
        int2 r0; r0.x = s.x; r0.y = __float_as_int(sqrtf(a.x));
        int2 r1; r1.x = s.y; r1.y = __float_as_int(sqrtf(a.y));
        int2 r2; r2.x = s.z; r2.y = __float_as_int(sqrtf(a.z));
        int2 r3; r3.x = s.w; r3.y = __float_as_int(sqrtf(a.w));
        g_perm[d.x * MAXDEG + p0] = r0;
        g_perm[d.y * MAXDEG + p1] = r1;
        g_perm[d.z * MAXDEG + p2] = r2;
        g_perm[d.w * MAXDEG + p3] = r3;
    }
}

// fused deghist + scan + order: 148 co-resident blocks, one software barrier
__global__ __launch_bounds__(256) void buildsort_kernel() {
    __shared__ int sh[DEGB];
    int tid = threadIdx.x;
    int gid = blockIdx.x * blockDim.x + tid;
    int stride = SORTBLK * 256;

    // Phase A: degree histogram (grid-strided)
    for (int i = gid; i < NN; i += stride) {
        int deg = g_cursor[i];
        atomicAdd(&g_deghist[deg < DEGB ? deg : DEGB - 1], 1);
    }

    // software grid barrier (all SORTBLK blocks are co-resident at 1/SM)
    __threadfence();
    __syncthreads();
    if (tid == 0) {
        atomicAdd(&g_bar, 1);
        while (atomicAdd(&g_bar, 0) < SORTBLK) { }
    }
    __syncthreads();

    // Phase B: every block scans the 256-bin histogram locally (redundant,
    // cheaper than a second barrier), then claims positions per bin.
    int v = g_deghist[tid];
    sh[tid] = v;
    __syncthreads();
    for (int off = 1; off < DEGB; off <<= 1) {
        int t = (tid >= off) ? sh[tid - off] : 0;
        __syncthreads();
        sh[tid] += t;
        __syncthreads();
    }
    __shared__ int base[DEGB];
    base[tid] = sh[tid] - v;     // exclusive base per bin
    __syncthreads();

    for (int i = gid; i < NN; i += stride) {
        int deg = g_cursor[i];
        int bin = deg < DEGB ? deg : DEGB - 1;
        int pos = base[bin] + atomicAdd(&g_degcur[bin], 1);
        int start = i * MAXDEG;
        g_nodeinfo[pos] = make_int4(i, start, start + deg, 0);
    }
}

// ---------------- iteration ----------------
// Persistent blocks + dynamic 64-node chunk tickets (descending degree = LPT).
// 4 lanes per node; lane l owns dims [4l, 4l+4).  256 thr = 64 nodes/chunk.
// Packed f32x2 arithmetic, BIT-IDENTICAL association to the scalar version:
//   d = fl(fl(xj + (-xi)) + EPS)  per lane (same as xj - xi + EPS scalar).
__global__ __launch_bounds__(256) void iterate_kernel(
        const float4* __restrict__ sin,
        const float4* __restrict__ x0v,
        float4* __restrict__ sout,
        int it) {
    __shared__ int s_chunk;
    int tid  = threadIdx.x;
    int lane = tid & 3;
    int slot = tid >> 2;

    const ull eps2 = pk2(EPSV, EPSV);

    while (true) {
        if (tid == 0) s_chunk = atomicAdd(&g_tickets[it], 1);
        __syncthreads();
        int c = s_chunk;
        __syncthreads();
        if (c >= NCHUNK) break;
        c = NCHUNK - 1 - c;                  // largest-degree chunks first (LPT)

        int idx = c * 64 + slot;
        if (idx < NN) {
            int4 info = g_nodeinfo[idx];
            int node  = info.x;
            float4 xi = sin[node * 4 + lane];

            ull nxi01 = pk2(-xi.x, -xi.y);   // exact negation
            ull nxi23 = pk2(-xi.z, -xi.w);
            ull num01 = 0, num23 = 0, den01 = 0, den23 = 0;

            #pragma unroll 2
            for (int e = info.y; e < info.z; ++e) {
                int2 rec  = g_perm[e];             // broadcast across the 4 lanes
                float we  = __int_as_float(rec.y);
                float4 xj = sin[rec.x * 4 + lane]; // coalesced 64B gather/group

                ull xj01 = pk2(xj.x, xj.y);
                ull xj23 = pk2(xj.z, xj.w);
                // same rounding sequence as scalar (xj - xi) + EPS
                ull d01 = add2(add2(xj01, nxi01), eps2);
                ull d23 = add2(add2(xj23, nxi23), eps2);
                float d0, d1, d2, d3;
                upk2(d01, d0, d1);
                upk2(d23, d2, d3);

                float w0 = __fdividef(we, fabsf(d0));   // MUFU.RCP|d| + FMUL
                float w1 = __fdividef(we, fabsf(d1));
                float w2 = __fdividef(we, fabsf(d2));
                float w3 = __fdividef(we, fabsf(d3));

                ull w01 = pk2(w0, w1);
                ull w23 = pk2(w2, w3);
                num01 = fma2(w01, xj01, num01);   // per-lane FFMA, same rounding
                num23 = fma2(w23, xj23, num23);
                den01 = add2(den01, w01);
                den23 = add2(den23, w23);
            }

            float n0, n1, n2, n3, e0, e1, e2, e3;
            upk2(num01, n0, n1);
            upk2(num23, n2, n3);
            upk2(den01, e0, e1);
            upk2(den23, e2, e3);

            float4 x0n = x0v[node * 4 + lane];
            float4 r;
            r.x = __fdividef(x0n.x + n0, 1.0f + e0);
            r.y = __fdividef(x0n.y + n1, 1.0f + e1);
            r.z = __fdividef(x0n.z + n2, 1.0f + e2);
            r.w = __fdividef(x0n.w + n3, 1.0f + e3);
            sout[node * 4 + lane] = r;
        }
    }
}

// ---------------- launch ----------------

extern "C" void kernel_launch(void* const* d_in, const int* in_sizes, int n_in,
                              void* d_out, int out_size) {
    const float* signal     = (const float*)d_in[0];
    const float* x0         = (const float*)d_in[1];
    const float* edge_attr  = (const float*)d_in[2];
    const int*   edge_index = (const int*)  d_in[3];
    float* out = (float*)d_out;

    float *bufA, *bufB;
    cudaGetSymbolAddress((void**)&bufA, g_bufA);
    cudaGetSymbolAddress((void**)&bufB, g_bufB);

    // build: zero + slot scatter + fused degree sort (3 kernels)
    zero_kernel<<<(NN + 255) / 256, 256>>>();
    scatter_kernel<<<(EE / 4 + 255) / 256, 256>>>(
        (const int4*)edge_index,
        (const int4*)(edge_index + EE),
        (const float4*)edge_attr);
    buildsort_kernel<<<SORTBLK, 256>>>();

    const float4* x0v = (const float4*)x0;

    // itr = 5: signal -> A -> B -> A -> B -> out  (persistent, ticket-scheduled)
    iterate_kernel<<<PBLOCKS, 256>>>((const float4*)signal, x0v, (float4*)bufA, 0);
    iterate_kernel<<<PBLOCKS, 256>>>((const float4*)bufA,   x0v, (float4*)bufB, 1);
    iterate_kernel<<<PBLOCKS, 256>>>((const float4*)bufB,   x0v, (float4*)bufA, 2);
    iterate_kernel<<<PBLOCKS, 256>>>((const float4*)bufA,   x0v, (float4*)bufB, 3);
    iterate_kernel<<<PBLOCKS, 256>>>((const float4*)bufB,   x0v, (float4*)out,  4);
}

// round 16
// speedup vs baseline: 1.0737x; 1.0737x over previous
#include <cuda_runtime.h>
#include <cuda_bf16.h>

#define NN 100000
#define EE 3200000
#define DD 16
#define EPSV 1e-5f
#define DEGB 256
#define MAXDEG 128           // Poisson(32): P(deg>=96) ~ 1e-19; 128 is safe
#define NCHUNK 1563          // ceil(NN/64) 64-node chunks
#define PBLOCKS 1184         // 8 blocks/SM * 148 SMs
#define SORTBLK 148          // 1 block/SM -> co-residency guaranteed

// ---- static device scratch (allocation-free rule) ----
__device__ int      g_cursor[NN];          // per-node fill cursor == final degree
__device__ int      g_deghist[DEGB];
__device__ int      g_degcur[DEGB];        // claim counters (start at 0)
__device__ int      g_tickets[8];          // per-iteration ticket counters
__device__ int      g_bar;                 // software grid barrier arrive count
__device__ int4     g_nodeinfo[NN];        // {node, start, end, 0}, degree-sorted
__device__ int2     g_perm[NN * MAXDEG];   // fixed 128-record slot per node
__device__ float    g_bufA[NN * DD];
__device__ float    g_bufB[NN * DD];

// ---------------- build ----------------

__global__ void zero_kernel() {
    int i = blockIdx.x * blockDim.x + threadIdx.x;
    if (i < NN) g_cursor[i] = 0;
    if (i < DEGB) { g_deghist[i] = 0; g_degcur[i] = 0; }
    if (i < 8) g_tickets[i] = 0;
    if (i == 8) g_bar = 0;
}

// 4 edges per thread; slot-addressed scatter (no offsets needed)
__global__ void scatter_kernel(const int4* __restrict__ src4,
                               const int4* __restrict__ dst4,
                               const float4* __restrict__ attr4) {
    int i = blockIdx.x * blockDim.x + threadIdx.x;
    if (i < EE / 4) {
        int4   s = src4[i];
        int4   d = dst4[i];
        float4 a = attr4[i];
        int p0 = atomicAdd(&g_cursor[d.x], 1);
        int p1 = atomicAdd(&g_cursor[d.y], 1);
        int p2 = atomicAdd(&g_cursor[d.z], 1);
        int p3 = atomicAdd(&g_cursor[d.w], 1);
        int2 r0; r0.x = s.x; r0.y = __float_as_int(sqrtf(a.x));
        int2 r1; r1.x = s.y; r1.y = __float_as_int(sqrtf(a.y));
        int2 r2; r2.x = s.z; r2.y = __float_as_int(sqrtf(a.z));
        int2 r3; r3.x = s.w; r3.y = __float_as_int(sqrtf(a.w));
        g_perm[d.x * MAXDEG + p0] = r0;
        g_perm[d.y * MAXDEG + p1] = r1;
        g_perm[d.z * MAXDEG + p2] = r2;
        g_perm[d.w * MAXDEG + p3] = r3;
    }
}

// fused deghist + scan + order: 148 co-resident blocks, one software barrier
__global__ __launch_bounds__(256) void buildsort_kernel() {
    __shared__ int sh[DEGB];
    int tid = threadIdx.x;
    int gid = blockIdx.x * blockDim.x + tid;
    int stride = SORTBLK * 256;

    // Phase A: degree histogram (grid-strided)
    for (int i = gid; i < NN; i += stride) {
        int deg = g_cursor[i];
        atomicAdd(&g_deghist[deg < DEGB ? deg : DEGB - 1], 1);
    }

    // software grid barrier (all SORTBLK blocks are co-resident at 1/SM)
    __threadfence();
    __syncthreads();
    if (tid == 0) {
        atomicAdd(&g_bar, 1);
        while (atomicAdd(&g_bar, 0) < SORTBLK) { }
    }
    __syncthreads();

    // Phase B: every block scans the 256-bin histogram locally (redundant,
    // cheaper than a second barrier), then claims positions per bin.
    int v = g_deghist[tid];
    sh[tid] = v;
    __syncthreads();
    for (int off = 1; off < DEGB; off <<= 1) {
        int t = (tid >= off) ? sh[tid - off] : 0;
        __syncthreads();
        sh[tid] += t;
        __syncthreads();
    }
    // sh[b] is inclusive; exclusive base of bin b = sh[b] - hist[b]
    __shared__ int base[DEGB];
    base[tid] = sh[tid] - v;
    __syncthreads();

    for (int i = gid; i < NN; i += stride) {
        int deg = g_cursor[i];
        int bin = deg < DEGB ? deg : DEGB - 1;
        int pos = base[bin] + atomicAdd(&g_degcur[bin], 1);
        int start = i * MAXDEG;
        g_nodeinfo[pos] = make_int4(i, start, start + deg, 0);
    }
}

// ---------------- iteration ----------------
// Persistent blocks + dynamic 64-node chunk tickets (descending degree = LPT).
// 4 lanes per node; lane l owns dims [4l, 4l+4).  256 thr = 64 nodes/chunk.
__global__ __launch_bounds__(256) void iterate_kernel(
        const float4* __restrict__ sin,
        const float4* __restrict__ x0v,
        float4* __restrict__ sout,
        int it) {
    __shared__ int s_chunk;
    int tid  = threadIdx.x;
    int lane = tid & 3;
    int slot = tid >> 2;

    while (true) {
        if (tid == 0) s_chunk = atomicAdd(&g_tickets[it], 1);
        __syncthreads();
        int c = s_chunk;
        __syncthreads();
        if (c >= NCHUNK) break;
        c = NCHUNK - 1 - c;                  // largest-degree chunks first (LPT)

        int idx = c * 64 + slot;
        if (idx < NN) {
            int4 info = g_nodeinfo[idx];
            int node  = info.x;
            float4 xi = sin[node * 4 + lane];

            float4 num = make_float4(0.f, 0.f, 0.f, 0.f);
            float4 den = make_float4(0.f, 0.f, 0.f, 0.f);

            #pragma unroll 2
            for (int e = info.y; e < info.z; ++e) {
                int2 rec  = g_perm[e];             // broadcast across the 4 lanes
                float we  = __int_as_float(rec.y);
                float4 xj = sin[rec.x * 4 + lane]; // coalesced 64B gather/group

                float w0 = __fdividef(we, fabsf(xj.x - xi.x + EPSV));
                float w1 = __fdividef(we, fabsf(xj.y - xi.y + EPSV));
                float w2 = __fdividef(we, fabsf(xj.z - xi.z + EPSV));
                float w3 = __fdividef(we, fabsf(xj.w - xi.w + EPSV));
                num.x += w0 * xj.x;  den.x += w0;
                num.y += w1 * xj.y;  den.y += w1;
                num.z += w2 * xj.z;  den.z += w2;
                num.w += w3 * xj.w;  den.w += w3;
            }

            float4 x0n = x0v[node * 4 + lane];
            float4 r;
            r.x = __fdividef(x0n.x + num.x, 1.0f + den.x);
            r.y = __fdividef(x0n.y + num.y, 1.0f + den.y);
            r.z = __fdividef(x0n.z + num.z, 1.0f + den.z);
            r.w = __fdividef(x0n.w + num.w, 1.0f + den.w);
            sout[node * 4 + lane] = r;
        }
    }
}

// ---------------- launch ----------------

extern "C" void kernel_launch(void* const* d_in, const int* in_sizes, int n_in,
                              void* d_out, int out_size) {
    const float* signal     = (const float*)d_in[0];
    const float* x0         = (const float*)d_in[1];
    const float* edge_attr  = (const float*)d_in[2];
    const int*   edge_index = (const int*)  d_in[3];
    float* out = (float*)d_out;

    float *bufA, *bufB;
    cudaGetSymbolAddress((void**)&bufA, g_bufA);
    cudaGetSymbolAddress((void**)&bufB, g_bufB);

    // build: zero + slot scatter + fused degree sort (3 kernels)
    zero_kernel<<<(NN + 255) / 256, 256>>>();
    scatter_kernel<<<(EE / 4 + 255) / 256, 256>>>(
        (const int4*)edge_index,
        (const int4*)(edge_index + EE),
        (const float4*)edge_attr);
    buildsort_kernel<<<SORTBLK, 256>>>();

    const float4* x0v = (const float4*)x0;

    // itr = 5: signal -> A -> B -> A -> B -> out  (persistent, ticket-scheduled)
    iterate_kernel<<<PBLOCKS, 256>>>((const float4*)signal, x0v, (float4*)bufA, 0);
    iterate_kernel<<<PBLOCKS, 256>>>((const float4*)bufA,   x0v, (float4*)bufB, 1);
    iterate_kernel<<<PBLOCKS, 256>>>((const float4*)bufB,   x0v, (float4*)bufA, 2);
    iterate_kernel<<<PBLOCKS, 256>>>((const float4*)bufA,   x0v, (float4*)bufB, 3);
    iterate_kernel<<<PBLOCKS, 256>>>((const float4*)bufB,   x0v, (float4*)out,  4);
}